// round 3
// baseline (speedup 1.0000x reference)
#include <cuda_runtime.h>
#include <math.h>

// ---------------------------------------------------------------------------
// YoloLoss: predictions (N,7,7,90) f32, target (N,7,7,85) f32 -> 4 scalars
// Per-cell layout:
//   preds:  [0..79]=classes, [80]=obj2, [81..84]=box2, [85]=obj1, [86..89]=box1
//   target: [0..79]=classes, [80]=obj,  [81..84]=box
// Strategy: smem-tile staging (coalesced float4), thread-per-cell scalar math,
// thread-parallel class loss, single kernel with last-block-done reduction.
// ---------------------------------------------------------------------------

#define PRED_C 90
#define TGT_C  85

static constexpr int CELLS   = 64;    // cells per tile
static constexpr int THREADS = 256;   // 8 warps
static constexpr int NBLOCKS = 608;   // 4 per SM (152 SMs), smem-limited to 5

__device__ float    g_partials[NBLOCKS * 4];
__device__ unsigned g_count = 0;

__device__ __forceinline__ float iou_cxcywh(float ax, float ay, float aw, float ah,
                                            float bx, float by, float bw, float bh) {
    float ax1 = ax - aw * 0.5f, ay1 = ay - ah * 0.5f;
    float ax2 = ax + aw * 0.5f, ay2 = ay + ah * 0.5f;
    float bx1 = bx - bw * 0.5f, by1 = by - bh * 0.5f;
    float bx2 = bx + bw * 0.5f, by2 = by + bh * 0.5f;
    float iw = fmaxf(fminf(ax2, bx2) - fmaxf(ax1, bx1), 0.0f);
    float ih = fmaxf(fminf(ay2, by2) - fmaxf(ay1, by1), 0.0f);
    float inter  = iw * ih;
    float area_a = (ax2 - ax1) * (ay2 - ay1);
    float area_b = (bx2 - bx1) * (by2 - by1);
    return inter / (area_a + area_b - inter);
}

__device__ __forceinline__ float sgnsqrt(float x) {
    float s = (x > 0.0f) ? 1.0f : ((x < 0.0f) ? -1.0f : 0.0f);
    return s * sqrtf(fabsf(x) + 1e-6f);
}

__global__ __launch_bounds__(THREADS)
void yolo_loss_fused(const float* __restrict__ P, const float* __restrict__ T,
                     float* __restrict__ out, int ncells) {
    __shared__ __align__(16) float sp[CELLS * PRED_C];  // 23040 B
    __shared__ __align__(16) float st[CELLS * TGT_C];   // 21760 B
    __shared__ float  red[4][THREADS / 32];
    __shared__ double dred[4][THREADS / 32];
    __shared__ int    s_last;

    const unsigned FULL = 0xffffffffu;
    const int tid  = threadIdx.x;
    const int lane = tid & 31;
    const int wrp  = tid >> 5;

    float aC = 0.0f, aO = 0.0f, aN = 0.0f, aL = 0.0f;

    const int ntiles = (ncells + CELLS - 1) / CELLS;
    for (int tile = blockIdx.x; tile < ntiles; tile += gridDim.x) {
        const int cbase = tile * CELLS;
        const int cells = min(CELLS, ncells - cbase);

        // ---- Stage tile to smem (coalesced) ----
        if (cells == CELLS) {
            const float4* gp  = reinterpret_cast<const float4*>(P + (size_t)cbase * PRED_C);
            float4*       spv = reinterpret_cast<float4*>(sp);
            for (int i = tid; i < CELLS * PRED_C / 4; i += THREADS) spv[i] = gp[i];
            const float4* gt  = reinterpret_cast<const float4*>(T + (size_t)cbase * TGT_C);
            float4*       stv = reinterpret_cast<float4*>(st);
            for (int i = tid; i < CELLS * TGT_C / 4; i += THREADS) stv[i] = gt[i];
        } else {
            for (int i = tid; i < cells * PRED_C; i += THREADS)
                sp[i] = P[(size_t)cbase * PRED_C + i];
            for (int i = tid; i < cells * TGT_C; i += THREADS)
                st[i] = T[(size_t)cbase * TGT_C + i];
        }
        __syncthreads();

        // ---- Class loss: thread-parallel over cells*80 elements ----
        const int nclass = cells * 80;
        for (int e = tid; e < nclass; e += THREADS) {
            unsigned c = (unsigned)e / 80u;
            unsigned k = (unsigned)e - c * 80u;
            float obj = st[c * TGT_C + 80];
            float d   = fmaf(sp[c * PRED_C + k], obj, -st[c * TGT_C + k]);
            aL = fmaf(d, d, aL);
        }

        // ---- Scalar per-cell math: one thread per cell ----
        if (tid < cells) {
            const float* pc = sp + tid * PRED_C;
            const float* tc = st + tid * TGT_C;
            float obj = tc[80];
            float tbx = tc[81], tby = tc[82], tbw = tc[83], tbh = tc[84];
            float p80 = pc[80];
            float b2x = pc[81], b2y = pc[82], b2w = pc[83], b2h = pc[84];
            float p85 = pc[85];
            float b1x = pc[86], b1y = pc[87], b1w = pc[88], b1h = pc[89];

            float iou1 = iou_cxcywh(b1x, b1y, b1w, b1h, tbx, tby, tbw, tbh);
            float iou2 = iou_cxcywh(b2x, b2y, b2w, b2h, tbx, tby, tbw, tbh);
            bool pick2 = iou2 > iou1;   // numpy argmax: first max wins ties

            float bx = pick2 ? b2x : b1x;
            float bw = pick2 ? b2w : b1w;
            float bh = pick2 ? b2h : b1h;
            float op = pick2 ? p80 : p85;

            // pred_boxes = obj * chosen box; center loss uses cx only ([..., :-3])
            float dc = fmaf(obj, bx, -tbx);
            aC = fmaf(dc, dc, aC);
            float dw = sgnsqrt(obj * bw) - sqrtf(tbw);
            aC = fmaf(dw, dw, aC);
            float dh = sgnsqrt(obj * bh) - sqrtf(tbh);
            aC = fmaf(dh, dh, aC);

            float e1 = fmaf(obj, op, -obj);
            aO = fmaf(e1, e1, aO);
            float e2 = fmaf(1.0f - obj, op, -obj);
            aN = fmaf(e2, e2, aN);
        }
        __syncthreads();  // before smem reuse next tile
    }

    // ---- Block reduction ----
    #pragma unroll
    for (int off = 16; off > 0; off >>= 1) {
        aC += __shfl_xor_sync(FULL, aC, off);
        aO += __shfl_xor_sync(FULL, aO, off);
        aN += __shfl_xor_sync(FULL, aN, off);
        aL += __shfl_xor_sync(FULL, aL, off);
    }
    if (lane == 0) {
        red[0][wrp] = aC; red[1][wrp] = aO; red[2][wrp] = aN; red[3][wrp] = aL;
    }
    __syncthreads();
    if (tid == 0) {
        float s0 = 0, s1 = 0, s2 = 0, s3 = 0;
        #pragma unroll
        for (int w = 0; w < THREADS / 32; w++) {
            s0 += red[0][w]; s1 += red[1][w]; s2 += red[2][w]; s3 += red[3][w];
        }
        g_partials[blockIdx.x * 4 + 0] = s0;
        g_partials[blockIdx.x * 4 + 1] = s1;
        g_partials[blockIdx.x * 4 + 2] = s2;
        g_partials[blockIdx.x * 4 + 3] = s3;
        __threadfence();
        unsigned prev = atomicAdd(&g_count, 1u);
        s_last = (prev == gridDim.x - 1) ? 1 : 0;
    }
    __syncthreads();

    // ---- Last block finalizes ----
    if (s_last) {
        double v0 = 0, v1 = 0, v2 = 0, v3 = 0;
        for (int b = tid; b < (int)gridDim.x; b += THREADS) {
            v0 += (double)__ldcg(&g_partials[b * 4 + 0]);
            v1 += (double)__ldcg(&g_partials[b * 4 + 1]);
            v2 += (double)__ldcg(&g_partials[b * 4 + 2]);
            v3 += (double)__ldcg(&g_partials[b * 4 + 3]);
        }
        #pragma unroll
        for (int off = 16; off > 0; off >>= 1) {
            v0 += __shfl_xor_sync(FULL, v0, off);
            v1 += __shfl_xor_sync(FULL, v1, off);
            v2 += __shfl_xor_sync(FULL, v2, off);
            v3 += __shfl_xor_sync(FULL, v3, off);
        }
        if (lane == 0) {
            dred[0][wrp] = v0; dred[1][wrp] = v1; dred[2][wrp] = v2; dred[3][wrp] = v3;
        }
        __syncthreads();
        if (tid == 0) {
            double c = 0, o = 0, n = 0, cl = 0;
            #pragma unroll
            for (int w = 0; w < THREADS / 32; w++) {
                c += dred[0][w]; o += dred[1][w]; n += dred[2][w]; cl += dred[3][w];
            }
            out[0] = (float)(c * 5.0);   // coords (LAMBDA_COORDS)
            out[1] = (float)o;           // obj
            out[2] = (float)(n * 0.5);   // noobj (LAMBDA_NOOBJ)
            out[3] = (float)cl;          // classes
            atomicExch(&g_count, 0u);    // reset for next graph replay
        }
    }
}

extern "C" void kernel_launch(void* const* d_in, const int* in_sizes, int n_in,
                              void* d_out, int out_size) {
    const float* P = (const float*)d_in[0];   // predictions
    const float* T = (const float*)d_in[1];   // target
    float* out = (float*)d_out;

    int ncells = in_sizes[0] / PRED_C;        // 8192*7*7 = 401408

    yolo_loss_fused<<<NBLOCKS, THREADS>>>(P, T, out, ncells);
}

// round 4
// speedup vs baseline: 1.4636x; 1.4636x over previous
#include <cuda_runtime.h>
#include <math.h>

// ---------------------------------------------------------------------------
// YoloLoss: predictions (N,7,7,90) f32, target (N,7,7,85) f32 -> 4 scalars
// Warp-autonomous design: each warp owns groups of 32 cells.
//   Phase A (per cell): coalesced chunk loads, per-lane class loss, stash 15
//                       box scalars to per-warp smem (conflict-free stride 11).
//   Phase B: 32 cells' box/obj math done one-cell-per-lane in parallel.
// No block barriers in the hot loop. Last-block-done fused finalize.
// ---------------------------------------------------------------------------

#define PRED_C 90
#define TGT_C  85

static constexpr int THREADS = 256;
static constexpr int WARPS   = THREADS / 32;
static constexpr int NBLOCKS = 760;     // ~5/SM nominal; grid-stride balances
static constexpr int GRP     = 32;      // cells per warp-group

__device__ float    g_partials[NBLOCKS * 4];
__device__ unsigned g_count = 0;

__device__ __forceinline__ float iou_cxcywh(float ax, float ay, float aw, float ah,
                                            float bx, float by, float bw, float bh) {
    float ax1 = ax - aw * 0.5f, ay1 = ay - ah * 0.5f;
    float ax2 = ax + aw * 0.5f, ay2 = ay + ah * 0.5f;
    float bx1 = bx - bw * 0.5f, by1 = by - bh * 0.5f;
    float bx2 = bx + bw * 0.5f, by2 = by + bh * 0.5f;
    float iw = fmaxf(fminf(ax2, bx2) - fmaxf(ax1, bx1), 0.0f);
    float ih = fmaxf(fminf(ay2, by2) - fmaxf(ay1, by1), 0.0f);
    float inter  = iw * ih;
    float area_a = (ax2 - ax1) * (ay2 - ay1);
    float area_b = (bx2 - bx1) * (by2 - by1);
    return inter / (area_a + area_b - inter);
}

__device__ __forceinline__ float sgnsqrt(float x) {
    float s = (x > 0.0f) ? 1.0f : ((x < 0.0f) ? -1.0f : 0.0f);
    return s * sqrtf(fabsf(x) + 1e-6f);
}

__global__ __launch_bounds__(THREADS)
void yolo_loss_fused(const float* __restrict__ P, const float* __restrict__ T,
                     float* __restrict__ out, int ncells) {
    // Per-warp box stash. boxP stride 11 (gcd(11,32)=1 -> conflict-free reads),
    // boxT stride 5 (gcd(5,32)=1 -> conflict-free).
    __shared__ float boxP[WARPS][GRP][11];   // p80,b2x,b2y,b2w,b2h,p85,b1x,b1y,b1w,b1h
    __shared__ float boxT[WARPS][GRP][5];    // obj,tbx,tby,tbw,tbh
    __shared__ float  red[4][WARPS];
    __shared__ double dred[4][WARPS];
    __shared__ int    s_last;

    const unsigned FULL = 0xffffffffu;
    const int tid  = threadIdx.x;
    const int lane = tid & 31;
    const int wrp  = tid >> 5;

    const int warp_global = blockIdx.x * WARPS + wrp;
    const int nwarps      = gridDim.x * WARPS;
    const int ngroups     = (ncells + GRP - 1) / GRP;

    float aC = 0.0f, aO = 0.0f, aN = 0.0f, aL = 0.0f;

    const unsigned li = (unsigned)(lane - 16);   // chunk-2 stash index

    for (int grp = warp_global; grp < ngroups; grp += nwarps) {
        const int cbase = grp * GRP;

        // ---- Phase A: per-cell coalesced loads, class loss, box stash ----
        #pragma unroll 4
        for (int c = 0; c < GRP; c++) {
            int cell = cbase + c;
            if (cell >= ncells) break;
            const float* p = P + (size_t)cell * PRED_C;
            const float* t = T + (size_t)cell * TGT_C;

            float p0 = p[lane];
            float p1 = p[32 + lane];
            float p2 = (lane < PRED_C - 64) ? p[64 + lane] : 0.0f;   // lanes 0..25
            float t0 = t[lane];
            float t1 = t[32 + lane];
            float t2 = (lane < TGT_C - 64) ? t[64 + lane] : 0.0f;    // lanes 0..20

            float obj = __shfl_sync(FULL, t2, 16);   // target[80]

            float d0 = fmaf(p0, obj, -t0);  aL = fmaf(d0, d0, aL);   // cls 0..31
            float d1 = fmaf(p1, obj, -t1);  aL = fmaf(d1, d1, aL);   // cls 32..63
            if (lane < 16) {                                          // cls 64..79
                float d2 = fmaf(p2, obj, -t2);  aL = fmaf(d2, d2, aL);
            }

            if (li < 10u) boxP[wrp][c][li] = p2;   // preds[80..89]
            if (li < 5u)  boxT[wrp][c][li] = t2;   // target[80..84]
        }
        __syncwarp();

        // ---- Phase B: box math, one cell per lane ----
        if (cbase + lane < ncells) {
            const float* bp = boxP[wrp][lane];
            const float* bt = boxT[wrp][lane];
            float p80 = bp[0];
            float b2x = bp[1], b2y = bp[2], b2w = bp[3], b2h = bp[4];
            float p85 = bp[5];
            float b1x = bp[6], b1y = bp[7], b1w = bp[8], b1h = bp[9];
            float obj = bt[0];
            float tbx = bt[1], tby = bt[2], tbw = bt[3], tbh = bt[4];

            float iou1 = iou_cxcywh(b1x, b1y, b1w, b1h, tbx, tby, tbw, tbh);
            float iou2 = iou_cxcywh(b2x, b2y, b2w, b2h, tbx, tby, tbw, tbh);
            bool pick2 = iou2 > iou1;   // numpy argmax: first max wins ties

            float bx = pick2 ? b2x : b1x;
            float bw = pick2 ? b2w : b1w;
            float bh = pick2 ? b2h : b1h;
            float op = pick2 ? p80 : p85;

            // pred_boxes = obj * chosen box; center loss uses cx only ([..., :-3])
            float dc = fmaf(obj, bx, -tbx);
            aC = fmaf(dc, dc, aC);
            float dw = sgnsqrt(obj * bw) - sqrtf(tbw);
            aC = fmaf(dw, dw, aC);
            float dh = sgnsqrt(obj * bh) - sqrtf(tbh);
            aC = fmaf(dh, dh, aC);

            float e1 = fmaf(obj, op, -obj);
            aO = fmaf(e1, e1, aO);
            float e2 = fmaf(1.0f - obj, op, -obj);
            aN = fmaf(e2, e2, aN);
        }
        __syncwarp();   // before next group's stash overwrites
    }

    // ---- Block reduction ----
    #pragma unroll
    for (int off = 16; off > 0; off >>= 1) {
        aC += __shfl_xor_sync(FULL, aC, off);
        aO += __shfl_xor_sync(FULL, aO, off);
        aN += __shfl_xor_sync(FULL, aN, off);
        aL += __shfl_xor_sync(FULL, aL, off);
    }
    if (lane == 0) {
        red[0][wrp] = aC; red[1][wrp] = aO; red[2][wrp] = aN; red[3][wrp] = aL;
    }
    __syncthreads();
    if (tid == 0) {
        float s0 = 0, s1 = 0, s2 = 0, s3 = 0;
        #pragma unroll
        for (int w = 0; w < WARPS; w++) {
            s0 += red[0][w]; s1 += red[1][w]; s2 += red[2][w]; s3 += red[3][w];
        }
        g_partials[blockIdx.x * 4 + 0] = s0;
        g_partials[blockIdx.x * 4 + 1] = s1;
        g_partials[blockIdx.x * 4 + 2] = s2;
        g_partials[blockIdx.x * 4 + 3] = s3;
        __threadfence();
        unsigned prev = atomicAdd(&g_count, 1u);
        s_last = (prev == gridDim.x - 1) ? 1 : 0;
    }
    __syncthreads();

    // ---- Last block finalizes ----
    if (s_last) {
        double v0 = 0, v1 = 0, v2 = 0, v3 = 0;
        for (int b = tid; b < (int)gridDim.x; b += THREADS) {
            v0 += (double)__ldcg(&g_partials[b * 4 + 0]);
            v1 += (double)__ldcg(&g_partials[b * 4 + 1]);
            v2 += (double)__ldcg(&g_partials[b * 4 + 2]);
            v3 += (double)__ldcg(&g_partials[b * 4 + 3]);
        }
        #pragma unroll
        for (int off = 16; off > 0; off >>= 1) {
            v0 += __shfl_xor_sync(FULL, v0, off);
            v1 += __shfl_xor_sync(FULL, v1, off);
            v2 += __shfl_xor_sync(FULL, v2, off);
            v3 += __shfl_xor_sync(FULL, v3, off);
        }
        if (lane == 0) {
            dred[0][wrp] = v0; dred[1][wrp] = v1; dred[2][wrp] = v2; dred[3][wrp] = v3;
        }
        __syncthreads();
        if (tid == 0) {
            double c = 0, o = 0, n = 0, cl = 0;
            #pragma unroll
            for (int w = 0; w < WARPS; w++) {
                c += dred[0][w]; o += dred[1][w]; n += dred[2][w]; cl += dred[3][w];
            }
            out[0] = (float)(c * 5.0);   // coords (LAMBDA_COORDS)
            out[1] = (float)o;           // obj
            out[2] = (float)(n * 0.5);   // noobj (LAMBDA_NOOBJ)
            out[3] = (float)cl;          // classes
            atomicExch(&g_count, 0u);    // reset for next graph replay
        }
    }
}

extern "C" void kernel_launch(void* const* d_in, const int* in_sizes, int n_in,
                              void* d_out, int out_size) {
    const float* P = (const float*)d_in[0];   // predictions
    const float* T = (const float*)d_in[1];   // target
    float* out = (float*)d_out;

    int ncells = in_sizes[0] / PRED_C;        // 8192*7*7 = 401408

    yolo_loss_fused<<<NBLOCKS, THREADS>>>(P, T, out, ncells);
}

// round 5
// speedup vs baseline: 1.5869x; 1.0842x over previous
#include <cuda_runtime.h>
#include <math.h>

// ---------------------------------------------------------------------------
// YoloLoss: predictions (N,7,7,90) f32, target (N,7,7,85) f32 -> 4 scalars
// Warp-autonomous, work-stealing design. Per 32-cell group:
//   - preload obj vector (1 strided LDG, doubles as prefetch of target tails)
//   - Phase A per cell: 6 coalesced LDGs, class-loss FMAs (obj via shfl of
//     preloaded reg), predicated stash of 15 box scalars to smem
//   - Phase B: box/IoU math one-cell-per-lane
// No block barriers in hot loop; last-block-done fused finalize resets counters.
// ---------------------------------------------------------------------------

#define PRED_C 90
#define TGT_C  85

static constexpr int THREADS = 256;
static constexpr int WARPS   = THREADS / 32;
static constexpr int NBLOCKS = 608;     // ~one full wave
static constexpr int GRP     = 32;      // cells per warp-group

__device__ float    g_partials[NBLOCKS * 4];
__device__ unsigned g_work  = 0;   // work-stealing counter
__device__ unsigned g_count = 0;   // completion counter

__device__ __forceinline__ float iou_cxcywh(float ax, float ay, float aw, float ah,
                                            float bx, float by, float bw, float bh) {
    float ax1 = ax - aw * 0.5f, ay1 = ay - ah * 0.5f;
    float ax2 = ax + aw * 0.5f, ay2 = ay + ah * 0.5f;
    float bx1 = bx - bw * 0.5f, by1 = by - bh * 0.5f;
    float bx2 = bx + bw * 0.5f, by2 = by + bh * 0.5f;
    float iw = fmaxf(fminf(ax2, bx2) - fmaxf(ax1, bx1), 0.0f);
    float ih = fmaxf(fminf(ay2, by2) - fmaxf(ay1, by1), 0.0f);
    float inter  = iw * ih;
    float area_a = (ax2 - ax1) * (ay2 - ay1);
    float area_b = (bx2 - bx1) * (by2 - by1);
    return inter / (area_a + area_b - inter);
}

__device__ __forceinline__ float sgnsqrt(float x) {
    float s = (x > 0.0f) ? 1.0f : ((x < 0.0f) ? -1.0f : 0.0f);
    return s * sqrtf(fabsf(x) + 1e-6f);
}

__global__ __launch_bounds__(THREADS)
void yolo_loss_fused(const float* __restrict__ P, const float* __restrict__ T,
                     float* __restrict__ out, int ncells) {
    // Per-warp stash. Stride 11 / 5 (odd) -> conflict-free Phase B reads.
    __shared__ float boxP[WARPS][GRP][11];   // p80,b2x,b2y,b2w,b2h,p85,b1x..b1h
    __shared__ float boxT[WARPS][GRP][5];    // obj,tbx,tby,tbw,tbh
    __shared__ float  red[4][WARPS];
    __shared__ double dred[4][WARPS];
    __shared__ int    s_last;

    const unsigned FULL = 0xffffffffu;
    const int tid  = threadIdx.x;
    const int lane = tid & 31;
    const int wrp  = tid >> 5;

    const int ngroups = (ncells + GRP - 1) / GRP;

    float aC = 0.0f, aO = 0.0f, aN = 0.0f;
    float aL0 = 0.0f, aL1 = 0.0f, aL2 = 0.0f;

    const unsigned li = (unsigned)(lane - 16);   // chunk-2 stash index

    // ---- Work stealing: lane 0 fetches, broadcast; prefetch next id ----
    int cur;
    if (lane == 0) cur = (int)atomicAdd(&g_work, 1u);
    cur = __shfl_sync(FULL, cur, 0);

    while (cur < ngroups) {
        int nxt;
        if (lane == 0) nxt = (int)atomicAdd(&g_work, 1u);   // hidden under work
        nxt = __shfl_sync(FULL, nxt, 0);

        const int cbase = cur * GRP;

        // Preload per-lane obj (target[cell*85+80]); also warms target tail lines.
        int oc = min(cbase + lane, ncells - 1);
        float objv = T[(size_t)oc * TGT_C + 80];

        if (cbase + GRP <= ncells) {
            // ---------------- full group: clean pipelined loop ----------------
            #pragma unroll 4
            for (int c = 0; c < GRP; c++) {
                const float* p = P + (size_t)(cbase + c) * PRED_C;
                const float* t = T + (size_t)(cbase + c) * TGT_C;

                float p0 = p[lane];
                float p1 = p[32 + lane];
                float p2 = (lane < PRED_C - 64) ? p[64 + lane] : 0.0f;
                float t0 = t[lane];
                float t1 = t[32 + lane];
                float t2 = (lane < TGT_C - 64) ? t[64 + lane] : 0.0f;

                float obj = __shfl_sync(FULL, objv, c);   // no load dependency

                float d0 = fmaf(p0, obj, -t0);  aL0 = fmaf(d0, d0, aL0);
                float d1 = fmaf(p1, obj, -t1);  aL1 = fmaf(d1, d1, aL1);
                if (lane < 16) {
                    float d2 = fmaf(p2, obj, -t2);  aL2 = fmaf(d2, d2, aL2);
                }

                if (li < 10u) boxP[wrp][c][li] = p2;   // preds[80..89]
                if (li < 5u)  boxT[wrp][c][li] = t2;   // target[80..84]
            }
        } else {
            // ---------------- ragged tail (not taken for 401408) --------------
            for (int c = 0; c < GRP; c++) {
                int cell = cbase + c;
                if (cell >= ncells) break;
                const float* p = P + (size_t)cell * PRED_C;
                const float* t = T + (size_t)cell * TGT_C;
                float p0 = p[lane];
                float p1 = p[32 + lane];
                float p2 = (lane < PRED_C - 64) ? p[64 + lane] : 0.0f;
                float t0 = t[lane];
                float t1 = t[32 + lane];
                float t2 = (lane < TGT_C - 64) ? t[64 + lane] : 0.0f;
                float obj = __shfl_sync(FULL, objv, c);
                float d0 = fmaf(p0, obj, -t0);  aL0 = fmaf(d0, d0, aL0);
                float d1 = fmaf(p1, obj, -t1);  aL1 = fmaf(d1, d1, aL1);
                if (lane < 16) {
                    float d2 = fmaf(p2, obj, -t2);  aL2 = fmaf(d2, d2, aL2);
                }
                if (li < 10u) boxP[wrp][c][li] = p2;
                if (li < 5u)  boxT[wrp][c][li] = t2;
            }
        }
        __syncwarp();

        // ---- Phase B: box math, one cell per lane ----
        if (cbase + lane < ncells) {
            const float* bp = boxP[wrp][lane];
            const float* bt = boxT[wrp][lane];
            float p80 = bp[0];
            float b2x = bp[1], b2y = bp[2], b2w = bp[3], b2h = bp[4];
            float p85 = bp[5];
            float b1x = bp[6], b1y = bp[7], b1w = bp[8], b1h = bp[9];
            float obj = bt[0];
            float tbx = bt[1], tby = bt[2], tbw = bt[3], tbh = bt[4];

            float iou1 = iou_cxcywh(b1x, b1y, b1w, b1h, tbx, tby, tbw, tbh);
            float iou2 = iou_cxcywh(b2x, b2y, b2w, b2h, tbx, tby, tbw, tbh);
            bool pick2 = iou2 > iou1;   // numpy argmax: first max wins ties

            float bx = pick2 ? b2x : b1x;
            float bw = pick2 ? b2w : b1w;
            float bh = pick2 ? b2h : b1h;
            float op = pick2 ? p80 : p85;

            // pred_boxes = obj * chosen box; center loss uses cx only ([..., :-3])
            float dc = fmaf(obj, bx, -tbx);
            aC = fmaf(dc, dc, aC);
            float dw = sgnsqrt(obj * bw) - sqrtf(tbw);
            aC = fmaf(dw, dw, aC);
            float dh = sgnsqrt(obj * bh) - sqrtf(tbh);
            aC = fmaf(dh, dh, aC);

            float e1 = fmaf(obj, op, -obj);
            aO = fmaf(e1, e1, aO);
            float e2 = fmaf(1.0f - obj, op, -obj);
            aN = fmaf(e2, e2, aN);
        }
        __syncwarp();   // stash reuse next group

        cur = nxt;
    }

    float aL = (aL0 + aL1) + aL2;

    // ---- Block reduction ----
    #pragma unroll
    for (int off = 16; off > 0; off >>= 1) {
        aC += __shfl_xor_sync(FULL, aC, off);
        aO += __shfl_xor_sync(FULL, aO, off);
        aN += __shfl_xor_sync(FULL, aN, off);
        aL += __shfl_xor_sync(FULL, aL, off);
    }
    if (lane == 0) {
        red[0][wrp] = aC; red[1][wrp] = aO; red[2][wrp] = aN; red[3][wrp] = aL;
    }
    __syncthreads();
    if (tid == 0) {
        float s0 = 0, s1 = 0, s2 = 0, s3 = 0;
        #pragma unroll
        for (int w = 0; w < WARPS; w++) {
            s0 += red[0][w]; s1 += red[1][w]; s2 += red[2][w]; s3 += red[3][w];
        }
        g_partials[blockIdx.x * 4 + 0] = s0;
        g_partials[blockIdx.x * 4 + 1] = s1;
        g_partials[blockIdx.x * 4 + 2] = s2;
        g_partials[blockIdx.x * 4 + 3] = s3;
        __threadfence();
        unsigned prev = atomicAdd(&g_count, 1u);
        s_last = (prev == gridDim.x - 1) ? 1 : 0;
    }
    __syncthreads();

    // ---- Last block finalizes & resets counters for graph replay ----
    if (s_last) {
        double v0 = 0, v1 = 0, v2 = 0, v3 = 0;
        for (int b = tid; b < (int)gridDim.x; b += THREADS) {
            v0 += (double)__ldcg(&g_partials[b * 4 + 0]);
            v1 += (double)__ldcg(&g_partials[b * 4 + 1]);
            v2 += (double)__ldcg(&g_partials[b * 4 + 2]);
            v3 += (double)__ldcg(&g_partials[b * 4 + 3]);
        }
        #pragma unroll
        for (int off = 16; off > 0; off >>= 1) {
            v0 += __shfl_xor_sync(FULL, v0, off);
            v1 += __shfl_xor_sync(FULL, v1, off);
            v2 += __shfl_xor_sync(FULL, v2, off);
            v3 += __shfl_xor_sync(FULL, v3, off);
        }
        if (lane == 0) {
            dred[0][wrp] = v0; dred[1][wrp] = v1; dred[2][wrp] = v2; dred[3][wrp] = v3;
        }
        __syncthreads();
        if (tid == 0) {
            double c = 0, o = 0, n = 0, cl = 0;
            #pragma unroll
            for (int w = 0; w < WARPS; w++) {
                c += dred[0][w]; o += dred[1][w]; n += dred[2][w]; cl += dred[3][w];
            }
            out[0] = (float)(c * 5.0);   // coords (LAMBDA_COORDS)
            out[1] = (float)o;           // obj
            out[2] = (float)(n * 0.5);   // noobj (LAMBDA_NOOBJ)
            out[3] = (float)cl;          // classes
            atomicExch(&g_work, 0u);     // reset for next graph replay
            atomicExch(&g_count, 0u);
        }
    }
}

extern "C" void kernel_launch(void* const* d_in, const int* in_sizes, int n_in,
                              void* d_out, int out_size) {
    const float* P = (const float*)d_in[0];   // predictions
    const float* T = (const float*)d_in[1];   // target
    float* out = (float*)d_out;

    int ncells = in_sizes[0] / PRED_C;        // 8192*7*7 = 401408

    yolo_loss_fused<<<NBLOCKS, THREADS>>>(P, T, out, ncells);
}